// round 1
// baseline (speedup 1.0000x reference)
#include <cuda_runtime.h>
#include <cstdint>
#include <math.h>

#define DIM   512
#define CDIM  128
#define CSIZE 8192
#define MMAX  16384
#define EPSV  1e-6f

// ---------------- device scratch (no allocations allowed) ----------------
__device__ float g_h[CSIZE * DIM];            // 16 MB
__device__ float g_icb[CSIZE * DIM];          // 16 MB
__device__ float g_cc[CSIZE];                 // ||icb||^2 per code
__device__ float g_xx[MMAX];                  // ||x||^2 per query
__device__ unsigned long long g_keys[MMAX];   // packed (d2_bits<<32 | idx)
__device__ float g_rowloss[MMAX];             // per-row sum (x-q)^2

__device__ __forceinline__ float selu_f(float z) {
    const float a = 1.6732632423543772f;
    const float s = 1.0507009873554805f;
    return s * (z > 0.f ? z : a * expm1f(z));
}

// ---------------- init keys ----------------
__global__ void init_keys_k(int M) {
    int i = blockIdx.x * blockDim.x + threadIdx.x;
    if (i < M) g_keys[i] = ~0ULL;
}

// ---------------- generic 64x64x16 SGEMM: C = f(A)@B + bias (+ Ares) ----------------
__global__ void __launch_bounds__(256) gemm64_k(
    const float* __restrict__ A, const float* __restrict__ B,
    const float* __restrict__ bias, const float* __restrict__ Ares,
    float* __restrict__ C, int M, int N, int K, int doSelu)
{
    __shared__ float As[16][64];
    __shared__ float Bs[16][64];

    int tid = threadIdx.x;
    int tx = tid & 15, ty = tid >> 4;
    int m0 = blockIdx.y * 64, n0 = blockIdx.x * 64;

    int arow = tid >> 2, aq = (tid & 3) << 2;   // A tile: 64 rows x 16 k
    int brow = tid >> 4, bcol = (tid & 15) << 2; // B tile: 16 k x 64 n

    float acc[4][4];
#pragma unroll
    for (int i = 0; i < 4; i++)
#pragma unroll
        for (int j = 0; j < 4; j++) acc[i][j] = 0.f;

    for (int k0 = 0; k0 < K; k0 += 16) {
        float4 av = *(const float4*)(A + (size_t)(m0 + arow) * K + k0 + aq);
        if (doSelu) {
            av.x = selu_f(av.x); av.y = selu_f(av.y);
            av.z = selu_f(av.z); av.w = selu_f(av.w);
        }
        As[aq + 0][arow] = av.x; As[aq + 1][arow] = av.y;
        As[aq + 2][arow] = av.z; As[aq + 3][arow] = av.w;

        float4 bv = *(const float4*)(B + (size_t)(k0 + brow) * N + n0 + bcol);
        *(float4*)&Bs[brow][bcol] = bv;
        __syncthreads();

#pragma unroll
        for (int k = 0; k < 16; k++) {
            float a[4], b[4];
#pragma unroll
            for (int i = 0; i < 4; i++) a[i] = As[k][ty * 4 + i];
#pragma unroll
            for (int j = 0; j < 4; j++) b[j] = Bs[k][tx * 4 + j];
#pragma unroll
            for (int i = 0; i < 4; i++)
#pragma unroll
                for (int j = 0; j < 4; j++) acc[i][j] += a[i] * b[j];
        }
        __syncthreads();
    }

#pragma unroll
    for (int i = 0; i < 4; i++) {
        int m = m0 + ty * 4 + i;
#pragma unroll
        for (int j = 0; j < 4; j++) {
            int n = n0 + tx * 4 + j;
            float v = acc[i][j] + bias[n];
            if (Ares) v += Ares[(size_t)m * N + n];
            C[(size_t)m * N + n] = v;
        }
    }
}

// ---------------- per-row sum of squares (512 cols) ----------------
__global__ void rowsq_k(const float* __restrict__ A, float* __restrict__ outv) {
    int m = blockIdx.x;
    int tid = threadIdx.x;               // 128 threads
    const float* r = A + (size_t)m * DIM;
    float s = 0.f;
#pragma unroll
    for (int i = 0; i < 4; i++) { float v = r[tid + i * 128]; s += v * v; }
    for (int o = 16; o > 0; o >>= 1) s += __shfl_down_sync(0xffffffffu, s, o);
    __shared__ float sb[4];
    if ((tid & 31) == 0) sb[tid >> 5] = s;
    __syncthreads();
    if (tid == 0) outv[m] = sb[0] + sb[1] + sb[2] + sb[3];
}

// ---------------- fused distance GEMM + argmin ----------------
// d2(m,c) = (xx[m] - 2*dot(x_m,icb_c)) + cc[c]; argmin over c, first-min tie-break.
__global__ void __launch_bounds__(256) dist_argmin_k(const float* __restrict__ X)
{
    __shared__ float As[16][128];
    __shared__ float Bs[16][128];
    __shared__ unsigned long long red[128][17];

    int tid = threadIdx.x;
    int tx = tid & 15, ty = tid >> 4;
    int bn = blockIdx.x * 128;
    int bm = blockIdx.y * 128;

    float acc[8][8];
#pragma unroll
    for (int i = 0; i < 8; i++)
#pragma unroll
        for (int j = 0; j < 8; j++) acc[i][j] = 0.f;

    int lrow = tid >> 1;
    int lk = (tid & 1) * 8;
    const float* Xp = X + (size_t)(bm + lrow) * DIM + lk;
    const float* Cp = g_icb + (size_t)(bn + lrow) * DIM + lk;

    for (int k0 = 0; k0 < DIM; k0 += 16) {
        float4 a0 = *(const float4*)(Xp + k0);
        float4 a1 = *(const float4*)(Xp + k0 + 4);
        float4 b0 = *(const float4*)(Cp + k0);
        float4 b1 = *(const float4*)(Cp + k0 + 4);
        As[lk + 0][lrow] = a0.x; As[lk + 1][lrow] = a0.y;
        As[lk + 2][lrow] = a0.z; As[lk + 3][lrow] = a0.w;
        As[lk + 4][lrow] = a1.x; As[lk + 5][lrow] = a1.y;
        As[lk + 6][lrow] = a1.z; As[lk + 7][lrow] = a1.w;
        Bs[lk + 0][lrow] = b0.x; Bs[lk + 1][lrow] = b0.y;
        Bs[lk + 2][lrow] = b0.z; Bs[lk + 3][lrow] = b0.w;
        Bs[lk + 4][lrow] = b1.x; Bs[lk + 5][lrow] = b1.y;
        Bs[lk + 6][lrow] = b1.z; Bs[lk + 7][lrow] = b1.w;
        __syncthreads();

#pragma unroll
        for (int k = 0; k < 16; k++) {
            float a[8], b[8];
#pragma unroll
            for (int i = 0; i < 8; i++) a[i] = As[k][ty * 8 + i];
#pragma unroll
            for (int j = 0; j < 8; j++) b[j] = Bs[k][tx * 8 + j];
#pragma unroll
            for (int i = 0; i < 8; i++)
#pragma unroll
                for (int j = 0; j < 8; j++) acc[i][j] += a[i] * b[j];
        }
        __syncthreads();
    }

    float xxv[8], ccv[8];
#pragma unroll
    for (int i = 0; i < 8; i++) xxv[i] = g_xx[bm + ty * 8 + i];
#pragma unroll
    for (int j = 0; j < 8; j++) ccv[j] = g_cc[bn + tx * 8 + j];

#pragma unroll
    for (int i = 0; i < 8; i++) {
        float best = 3.4e38f;
        int bj = 0;
#pragma unroll
        for (int j = 0; j < 8; j++) {
            float t = __fmul_rn(acc[i][j], -2.0f);
            float d2 = __fadd_rn(__fadd_rn(xxv[i], t), ccv[j]);
            if (d2 < best) { best = d2; bj = j; }   // strict < keeps lowest j on ties
        }
        unsigned int fb = __float_as_uint(best);
        fb = (fb & 0x80000000u) ? ~fb : (fb | 0x80000000u);  // order-preserving
        red[ty * 8 + i][tx] =
            ((unsigned long long)fb << 32) | (unsigned)(bn + tx * 8 + bj);
    }
    __syncthreads();

    if (tid < 128) {
        unsigned long long kmin = red[tid][0];
#pragma unroll
        for (int t = 1; t < 16; t++) {
            unsigned long long v = red[tid][t];
            if (v < kmin) kmin = v;
        }
        atomicMin(&g_keys[bm + tid], kmin);
    }
}

// ---------------- gather + Householder rotation + loss partials ----------------
__global__ void rowfinish_k(const float* __restrict__ X, float* __restrict__ out,
                            int M, long long idx_off)
{
    int m = blockIdx.x;
    int tid = threadIdx.x;     // 128 threads
    unsigned long long key = g_keys[m];
    int idx = (int)(key & 0xffffffffu);

    const float* xr = X + (size_t)m * DIM;
    const float* qr = g_icb + (size_t)idx * DIM;

    float xv[4], qv[4];
    float sx2 = 0.f, sq2 = 0.f, sd2 = 0.f;
#pragma unroll
    for (int i = 0; i < 4; i++) {
        int d = tid + i * 128;
        xv[i] = xr[d]; qv[i] = qr[d];
        sx2 += xv[i] * xv[i];
        sq2 += qv[i] * qv[i];
        float df = xv[i] - qv[i];
        sd2 += df * df;
    }

    __shared__ float sb[16];
    // reduce sx2, sq2, sd2
    {
        float v0 = sx2, v1 = sq2, v2 = sd2;
        for (int o = 16; o > 0; o >>= 1) {
            v0 += __shfl_down_sync(0xffffffffu, v0, o);
            v1 += __shfl_down_sync(0xffffffffu, v1, o);
            v2 += __shfl_down_sync(0xffffffffu, v2, o);
        }
        int w = tid >> 5;
        if ((tid & 31) == 0) { sb[w] = v0; sb[4 + w] = v1; sb[8 + w] = v2; }
        __syncthreads();
        sx2 = sb[0] + sb[1] + sb[2] + sb[3];
        sq2 = sb[4] + sb[5] + sb[6] + sb[7];
        sd2 = sb[8] + sb[9] + sb[10] + sb[11];
        __syncthreads();
    }

    float ns = sqrtf(sx2), nt = sqrtf(sq2);
    float ins = 1.f / fmaxf(ns, EPSV);
    float inv_t = 1.f / fmaxf(nt, EPSV);

    float wv[4];
    float sw2 = 0.f, sxw = 0.f;
#pragma unroll
    for (int i = 0; i < 4; i++) {
        float w = xv[i] * ins + qv[i] * inv_t;
        wv[i] = w;
        sw2 += w * w;
        sxw += xv[i] * w;
    }
    {
        float v0 = sw2, v1 = sxw;
        for (int o = 16; o > 0; o >>= 1) {
            v0 += __shfl_down_sync(0xffffffffu, v0, o);
            v1 += __shfl_down_sync(0xffffffffu, v1, o);
        }
        int w = tid >> 5;
        if ((tid & 31) == 0) { sb[w] = v0; sb[4 + w] = v1; }
        __syncthreads();
        sw2 = sb[0] + sb[1] + sb[2] + sb[3];
        sxw = sb[4] + sb[5] + sb[6] + sb[7];
        __syncthreads();
    }

    float iwn = 1.f / fmaxf(sqrtf(sw2), EPSV);
    float xdw = sxw * iwn;         // x . w
    float xdu = sx2 * ins;         // x . u
    float scl = nt * ins;          // nt / max(ns, eps)

    float* orow = out + (size_t)m * DIM;
#pragma unroll
    for (int i = 0; i < 4; i++) {
        int d = tid + i * 128;
        float r = xv[i] - 2.f * xdw * (wv[i] * iwn) + 2.f * xdu * (qv[i] * inv_t);
        orow[d] = r * scl;
    }

    if (tid == 0) {
        g_rowloss[m] = sd2;
        if (idx_off >= 0) out[idx_off + m] = (float)idx;
    }
}

// ---------------- final loss reduce ----------------
__global__ void loss_k(float* __restrict__ out, int M, long long pos) {
    int tid = threadIdx.x;   // 256
    float s = 0.f;
    for (int i = tid; i < M; i += 256) s += g_rowloss[i];
    for (int o = 16; o > 0; o >>= 1) s += __shfl_down_sync(0xffffffffu, s, o);
    __shared__ float sb[8];
    if ((tid & 31) == 0) sb[tid >> 5] = s;
    __syncthreads();
    if (tid == 0) {
        float t = 0.f;
        for (int i = 0; i < 8; i++) t += sb[i];
        if (pos >= 0) out[pos] = 1.25f * t / (float)((size_t)M * DIM);
    }
}

// ---------------- host launcher (graph-capturable) ----------------
extern "C" void kernel_launch(void* const* d_in, const int* in_sizes, int n_in,
                              void* d_out, int out_size)
{
    const float* x  = (const float*)d_in[0];
    const float* cb = (const float*)d_in[1];
    const float* W1 = (const float*)d_in[2];
    const float* b1 = (const float*)d_in[3];
    const float* W2 = (const float*)d_in[4];
    const float* b2 = (const float*)d_in[5];
    float* out = (float*)d_out;

    int M = in_sizes[0] / DIM;            // 16384
    long long NQ = (long long)M * DIM;    // 8388608

    long long idx_off = (out_size >= NQ + M) ? NQ : -1;
    long long loss_pos = -1;
    if (out_size >= NQ + M + 1) loss_pos = NQ + M;
    else if (out_size == NQ + 1) loss_pos = NQ;

    float *p_h, *p_icb, *p_cc, *p_xx;
    cudaGetSymbolAddress((void**)&p_h,   g_h);
    cudaGetSymbolAddress((void**)&p_icb, g_icb);
    cudaGetSymbolAddress((void**)&p_cc,  g_cc);
    cudaGetSymbolAddress((void**)&p_xx,  g_xx);

    // kill the 0xAA poison for any tail elements we don't explicitly cover
    cudaMemsetAsync(d_out, 0, (size_t)out_size * sizeof(float));

    init_keys_k<<<(M + 255) / 256, 256>>>(M);

    // h = cb @ W1 + b1
    gemm64_k<<<dim3(DIM / 64, CSIZE / 64), 256>>>(cb, W1, b1, nullptr, p_h,
                                                  CSIZE, DIM, CDIM, 0);
    // icb = h + selu(h) @ W2 + b2
    gemm64_k<<<dim3(DIM / 64, CSIZE / 64), 256>>>(p_h, W2, b2, p_h, p_icb,
                                                  CSIZE, DIM, DIM, 1);
    // norms
    rowsq_k<<<CSIZE, 128>>>(p_icb, p_cc);
    rowsq_k<<<M, 128>>>(x, p_xx);

    // fused distance GEMM + argmin
    dist_argmin_k<<<dim3(CSIZE / 128, M / 128), 256>>>(x);

    // gather + rotation + loss partials + outputs
    rowfinish_k<<<M, 128>>>(x, out, M, idx_off);
    loss_k<<<1, 256>>>(out, M, loss_pos);
}

// round 3
// speedup vs baseline: 2.1179x; 2.1179x over previous
#include <cuda_runtime.h>
#include <cuda_bf16.h>
#include <cstdint>
#include <math.h>

#define DIM   512
#define CDIM  128
#define CSIZE 8192
#define MMAX  16384
#define EPSV  1e-6f

// ---- dist kernel tiling ----
#define MT 128
#define NT 128
#define KC 32
#define NSTAGES (DIM / KC)        // 16
#define ROWB 80                   // 32 bf16 = 64B + 16B pad (conflict-free ldmatrix)
#define BUFSZ (128 * ROWB)        // 10240 B per operand buffer
#define OFF_AHI 0
#define OFF_ALO (1 * BUFSZ)
#define OFF_BHI (2 * BUFSZ)
#define OFF_BLO (3 * BUFSZ)
#define SM_STAGE (4 * BUFSZ)      // 40960
#define SM_BUF0 1024              // [0..512) = cc tile
#define SM_TOTAL (SM_BUF0 + 2 * SM_STAGE)   // 82944

// ---------------- device scratch ----------------
__device__ float g_h[CSIZE * DIM];
__device__ float g_icb[CSIZE * DIM];
__device__ float g_cc[CSIZE];
__device__ float g_xx[MMAX];
__device__ unsigned long long g_keys[MMAX];
__device__ float g_rowloss[MMAX];
__device__ __nv_bfloat16 g_xhi[MMAX * DIM];
__device__ __nv_bfloat16 g_xlo[MMAX * DIM];
__device__ __nv_bfloat16 g_chi[CSIZE * DIM];
__device__ __nv_bfloat16 g_clo[CSIZE * DIM];

// ---------------- helpers ----------------
__device__ __forceinline__ uint32_t smem_u32(const void* p) {
    uint32_t a;
    asm("{ .reg .u64 t; cvta.to.shared.u64 t, %1; cvt.u32.u64 %0, t; }"
        : "=r"(a) : "l"(p));
    return a;
}

#define CP_ASYNC16(dst, src) \
    asm volatile("cp.async.cg.shared.global [%0], [%1], 16;" :: "r"(dst), "l"(src))
#define CP_COMMIT() asm volatile("cp.async.commit_group;" ::: "memory")
#define CP_WAIT1() asm volatile("cp.async.wait_group 1;" ::: "memory")
#define CP_WAIT0() asm volatile("cp.async.wait_group 0;" ::: "memory")

__device__ __forceinline__ void ldm_x4(uint32_t* r, uint32_t addr) {
    asm volatile("ldmatrix.sync.aligned.m8n8.x4.shared.b16 {%0,%1,%2,%3}, [%4];"
                 : "=r"(r[0]), "=r"(r[1]), "=r"(r[2]), "=r"(r[3]) : "r"(addr));
}
__device__ __forceinline__ void ldm_x2(uint32_t* r, uint32_t addr) {
    asm volatile("ldmatrix.sync.aligned.m8n8.x2.shared.b16 {%0,%1}, [%2];"
                 : "=r"(r[0]), "=r"(r[1]) : "r"(addr));
}
__device__ __forceinline__ void mma_bf16(float* c, const uint32_t* a, const uint32_t* b) {
    asm volatile(
        "mma.sync.aligned.m16n8k16.row.col.f32.bf16.bf16.f32 "
        "{%0,%1,%2,%3}, {%4,%5,%6,%7}, {%8,%9}, {%0,%1,%2,%3};"
        : "+f"(c[0]), "+f"(c[1]), "+f"(c[2]), "+f"(c[3])
        : "r"(a[0]), "r"(a[1]), "r"(a[2]), "r"(a[3]), "r"(b[0]), "r"(b[1]));
}

__device__ __forceinline__ float selu_f(float z) {
    const float a = 1.6732632423543772f;
    const float s = 1.0507009873554805f;
    return s * (z > 0.f ? z : a * expm1f(z));
}

// ---------------- init keys ----------------
__global__ void init_keys_k(int M) {
    int i = blockIdx.x * blockDim.x + threadIdx.x;
    if (i < M) g_keys[i] = ~0ULL;
}

// ---------------- fp32 -> bf16 hi/lo split ----------------
__global__ void conv_k(const float* __restrict__ s, __nv_bfloat16* __restrict__ hi,
                       __nv_bfloat16* __restrict__ lo, int n) {
    int i = (blockIdx.x * blockDim.x + threadIdx.x) * 4;
    if (i >= n) return;
    float4 v = *(const float4*)(s + i);
    float vv[4] = {v.x, v.y, v.z, v.w};
    __nv_bfloat162 h2[2], l2[2];
#pragma unroll
    for (int q = 0; q < 2; q++) {
        __nv_bfloat16 ha = __float2bfloat16(vv[2 * q]);
        __nv_bfloat16 hb = __float2bfloat16(vv[2 * q + 1]);
        __nv_bfloat16 la = __float2bfloat16(vv[2 * q] - __bfloat162float(ha));
        __nv_bfloat16 lb = __float2bfloat16(vv[2 * q + 1] - __bfloat162float(hb));
        h2[q] = __nv_bfloat162(ha, hb);
        l2[q] = __nv_bfloat162(la, lb);
    }
    *(__nv_bfloat162*)(hi + i) = h2[0];
    *(__nv_bfloat162*)(hi + i + 2) = h2[1];
    *(__nv_bfloat162*)(lo + i) = l2[0];
    *(__nv_bfloat162*)(lo + i + 2) = l2[1];
}

// ---------------- 128x128 SGEMM: C = f(A)@B + bias (+ Ares) ----------------
__global__ void __launch_bounds__(256) gemm128_k(
    const float* __restrict__ A, const float* __restrict__ B,
    const float* __restrict__ bias, const float* __restrict__ Ares,
    float* __restrict__ C, int M, int N, int K, int doSelu)
{
    __shared__ float As[16][128];
    __shared__ float Bs[16][128];
    int tid = threadIdx.x;
    int tx = tid & 15, ty = tid >> 4;
    int m0 = blockIdx.y * 128, n0 = blockIdx.x * 128;

    int arow = tid >> 1, ak = (tid & 1) * 8;
    int brow = tid >> 4, bcol = (tid & 15) * 8;

    float acc[8][8];
#pragma unroll
    for (int i = 0; i < 8; i++)
#pragma unroll
        for (int j = 0; j < 8; j++) acc[i][j] = 0.f;

    for (int k0 = 0; k0 < K; k0 += 16) {
        float4 a0 = *(const float4*)(A + (size_t)(m0 + arow) * K + k0 + ak);
        float4 a1 = *(const float4*)(A + (size_t)(m0 + arow) * K + k0 + ak + 4);
        if (doSelu) {
            a0.x = selu_f(a0.x); a0.y = selu_f(a0.y); a0.z = selu_f(a0.z); a0.w = selu_f(a0.w);
            a1.x = selu_f(a1.x); a1.y = selu_f(a1.y); a1.z = selu_f(a1.z); a1.w = selu_f(a1.w);
        }
        As[ak + 0][arow] = a0.x; As[ak + 1][arow] = a0.y;
        As[ak + 2][arow] = a0.z; As[ak + 3][arow] = a0.w;
        As[ak + 4][arow] = a1.x; As[ak + 5][arow] = a1.y;
        As[ak + 6][arow] = a1.z; As[ak + 7][arow] = a1.w;

        float4 b0 = *(const float4*)(B + (size_t)(k0 + brow) * N + n0 + bcol);
        float4 b1 = *(const float4*)(B + (size_t)(k0 + brow) * N + n0 + bcol + 4);
        *(float4*)&Bs[brow][bcol] = b0;
        *(float4*)&Bs[brow][bcol + 4] = b1;
        __syncthreads();

#pragma unroll
        for (int k = 0; k < 16; k++) {
            float a[8], b[8];
#pragma unroll
            for (int i = 0; i < 8; i++) a[i] = As[k][ty * 8 + i];
#pragma unroll
            for (int j = 0; j < 8; j++) b[j] = Bs[k][tx * 8 + j];
#pragma unroll
            for (int i = 0; i < 8; i++)
#pragma unroll
                for (int j = 0; j < 8; j++) acc[i][j] += a[i] * b[j];
        }
        __syncthreads();
    }

#pragma unroll
    for (int i = 0; i < 8; i++) {
        int m = m0 + ty * 8 + i;
#pragma unroll
        for (int j = 0; j < 8; j++) {
            int n = n0 + tx * 8 + j;
            float v = acc[i][j] + bias[n];
            if (Ares) v += Ares[(size_t)m * N + n];
            C[(size_t)m * N + n] = v;
        }
    }
}

// ---------------- per-row sum of squares ----------------
__global__ void rowsq_k(const float* __restrict__ A, float* __restrict__ outv) {
    int m = blockIdx.x;
    int tid = threadIdx.x;
    const float* r = A + (size_t)m * DIM;
    float s = 0.f;
#pragma unroll
    for (int i = 0; i < 4; i++) { float v = r[tid + i * 128]; s += v * v; }
    for (int o = 16; o > 0; o >>= 1) s += __shfl_down_sync(0xffffffffu, s, o);
    __shared__ float sb[4];
    if ((tid & 31) == 0) sb[tid >> 5] = s;
    __syncthreads();
    if (tid == 0) outv[m] = sb[0] + sb[1] + sb[2] + sb[3];
}

// ---------------- HMMA distance GEMM + fused argmin ----------------
// dot(m,c) = xhi.chi + xhi.clo + xlo.chi ; d2 = xx - 2*dot + cc ; argmin over c.
__global__ void __launch_bounds__(256, 1) dist_mma_k() {
    extern __shared__ char smem[];
    uint32_t sbase = smem_u32(smem);
    float* s_cc = (float*)smem;

    int tid = threadIdx.x;
    int wid = tid >> 5, lane = tid & 31;
    int bn = blockIdx.x * NT;
    int bm = blockIdx.y * MT;

    int wm = (wid & 3) * 32;     // warp m-offset within tile
    int wn = (wid >> 2) * 64;    // warp n-offset within tile

    if (tid < NT) s_cc[tid] = g_cc[bn + tid];

    float acc[2][8][4];
#pragma unroll
    for (int i = 0; i < 2; i++)
#pragma unroll
        for (int j = 0; j < 8; j++)
#pragma unroll
            for (int r = 0; r < 4; r++) acc[i][j][r] = 0.f;

    // -------- loader lambda: stage s into buffer (s&1) --------
    const __nv_bfloat16* xhi = g_xhi;
    const __nv_bfloat16* xlo = g_xlo;
    const __nv_bfloat16* chi = g_chi;
    const __nv_bfloat16* clo = g_clo;

    auto issue_stage = [&](int s) {
        int b = s & 1;
        int k0 = s * KC;
        uint32_t buf = sbase + SM_BUF0 + b * SM_STAGE;
#pragma unroll
        for (int r = 0; r < 2; r++) {
            int c = tid + 256 * r;
            int row = c >> 2, part = c & 3;
            uint32_t so = (uint32_t)(row * ROWB + part * 16);
            size_t goA = (size_t)(bm + row) * DIM + k0 + part * 8;
            size_t goB = (size_t)(bn + row) * DIM + k0 + part * 8;
            CP_ASYNC16(buf + OFF_AHI + so, xhi + goA);
            CP_ASYNC16(buf + OFF_ALO + so, xlo + goA);
            CP_ASYNC16(buf + OFF_BHI + so, chi + goB);
            CP_ASYNC16(buf + OFF_BLO + so, clo + goB);
        }
    };

    issue_stage(0);
    CP_COMMIT();

    for (int s = 0; s < NSTAGES; s++) {
        if (s + 1 < NSTAGES) {
            issue_stage(s + 1);
            CP_COMMIT();
            CP_WAIT1();
        } else {
            CP_WAIT0();
        }
        __syncthreads();

        uint32_t buf = sbase + SM_BUF0 + (s & 1) * SM_STAGE;
#pragma unroll
        for (int kk = 0; kk < 2; kk++) {
            int kb = kk * 32;  // byte offset of k-halves (16 elems * 2B)
            uint32_t arow = (uint32_t)((wm + (lane & 15)) * ROWB + kb + (lane >> 4) * 16);
            uint32_t ahi0[4], ahi1[4], alo0[4], alo1[4];
            ldm_x4(ahi0, buf + OFF_AHI + arow);
            ldm_x4(ahi1, buf + OFF_AHI + arow + 16 * ROWB);
            ldm_x4(alo0, buf + OFF_ALO + arow);
            ldm_x4(alo1, buf + OFF_ALO + arow + 16 * ROWB);

            uint32_t brow_base =
                (uint32_t)((wn + (lane & 7)) * ROWB + kb + ((lane >> 3) & 1) * 16);
#pragma unroll
            for (int j = 0; j < 8; j++) {
                uint32_t bo = brow_base + (uint32_t)(j * 8 * ROWB);
                uint32_t bhi[2], blo[2];
                ldm_x2(bhi, buf + OFF_BHI + bo);
                ldm_x2(blo, buf + OFF_BLO + bo);
                mma_bf16(acc[0][j], ahi0, bhi);
                mma_bf16(acc[0][j], ahi0, blo);
                mma_bf16(acc[0][j], alo0, bhi);
                mma_bf16(acc[1][j], ahi1, bhi);
                mma_bf16(acc[1][j], ahi1, blo);
                mma_bf16(acc[1][j], alo1, bhi);
            }
        }
        __syncthreads();
    }

    // -------- epilogue: d2 + argmin --------
    int q = lane >> 2, t = lane & 3;
#pragma unroll
    for (int i = 0; i < 2; i++) {
#pragma unroll
        for (int h = 0; h < 2; h++) {
            int row = bm + wm + i * 16 + h * 8 + q;
            float xxv = g_xx[row];
            float best = 3.4e38f;
            int bidx = 0;
#pragma unroll
            for (int j = 0; j < 8; j++) {
#pragma unroll
                for (int e = 0; e < 2; e++) {
                    int col = wn + j * 8 + 2 * t + e;
                    float dot = acc[i][j][h * 2 + e];
                    float d2 = __fadd_rn(__fadd_rn(xxv, __fmul_rn(dot, -2.0f)), s_cc[col]);
                    if (d2 < best) { best = d2; bidx = col; }
                }
            }
            unsigned int fb = __float_as_uint(best);
            fb = (fb & 0x80000000u) ? ~fb : (fb | 0x80000000u);
            unsigned long long key =
                ((unsigned long long)fb << 32) | (unsigned)(bn + bidx);
            unsigned long long o1 = __shfl_xor_sync(0xffffffffu, key, 1);
            if (o1 < key) key = o1;
            unsigned long long o2 = __shfl_xor_sync(0xffffffffu, key, 2);
            if (o2 < key) key = o2;
            if (t == 0) atomicMin(&g_keys[row], key);
        }
    }
}

// ---------------- gather + Householder rotation + loss ----------------
__global__ void rowfinish_k(const float* __restrict__ X, float* __restrict__ out,
                            int M, long long idx_off)
{
    int m = blockIdx.x;
    int tid = threadIdx.x;
    unsigned long long key = g_keys[m];
    int idx = (int)(key & 0xffffffffu);

    const float* xr = X + (size_t)m * DIM;
    const float* qr = g_icb + (size_t)idx * DIM;

    float xv[4], qv[4];
    float sx2 = 0.f, sq2 = 0.f, sd2 = 0.f;
#pragma unroll
    for (int i = 0; i < 4; i++) {
        int d = tid + i * 128;
        xv[i] = xr[d]; qv[i] = qr[d];
        sx2 += xv[i] * xv[i];
        sq2 += qv[i] * qv[i];
        float df = xv[i] - qv[i];
        sd2 += df * df;
    }

    __shared__ float sb[16];
    {
        float v0 = sx2, v1 = sq2, v2 = sd2;
        for (int o = 16; o > 0; o >>= 1) {
            v0 += __shfl_down_sync(0xffffffffu, v0, o);
            v1 += __shfl_down_sync(0xffffffffu, v1, o);
            v2 += __shfl_down_sync(0xffffffffu, v2, o);
        }
        int w = tid >> 5;
        if ((tid & 31) == 0) { sb[w] = v0; sb[4 + w] = v1; sb[8 + w] = v2; }
        __syncthreads();
        sx2 = sb[0] + sb[1] + sb[2] + sb[3];
        sq2 = sb[4] + sb[5] + sb[6] + sb[7];
        sd2 = sb[8] + sb[9] + sb[10] + sb[11];
        __syncthreads();
    }

    float ns = sqrtf(sx2), nt = sqrtf(sq2);
    float ins = 1.f / fmaxf(ns, EPSV);
    float inv_t = 1.f / fmaxf(nt, EPSV);

    float wv[4];
    float sw2 = 0.f, sxw = 0.f;
#pragma unroll
    for (int i = 0; i < 4; i++) {
        float w = xv[i] * ins + qv[i] * inv_t;
        wv[i] = w;
        sw2 += w * w;
        sxw += xv[i] * w;
    }
    {
        float v0 = sw2, v1 = sxw;
        for (int o = 16; o > 0; o >>= 1) {
            v0 += __shfl_down_sync(0xffffffffu, v0, o);
            v1 += __shfl_down_sync(0xffffffffu, v1, o);
        }
        int w = tid >> 5;
        if ((tid & 31) == 0) { sb[w] = v0; sb[4 + w] = v1; }
        __syncthreads();
        sw2 = sb[0] + sb[1] + sb[2] + sb[3];
        sxw = sb[4] + sb[5] + sb[6] + sb[7];
        __syncthreads();
    }

    float iwn = 1.f / fmaxf(sqrtf(sw2), EPSV);
    float xdw = sxw * iwn;
    float xdu = sx2 * ins;
    float scl = nt * ins;

    float* orow = out + (size_t)m * DIM;
#pragma unroll
    for (int i = 0; i < 4; i++) {
        int d = tid + i * 128;
        float r = xv[i] - 2.f * xdw * (wv[i] * iwn) + 2.f * xdu * (qv[i] * inv_t);
        orow[d] = r * scl;
    }

    if (tid == 0) {
        g_rowloss[m] = sd2;
        if (idx_off >= 0) out[idx_off + m] = (float)idx;
    }
}

__global__ void loss_k(float* __restrict__ out, int M, long long pos) {
    int tid = threadIdx.x;
    float s = 0.f;
    for (int i = tid; i < M; i += 256) s += g_rowloss[i];
    for (int o = 16; o > 0; o >>= 1) s += __shfl_down_sync(0xffffffffu, s, o);
    __shared__ float sb[8];
    if ((tid & 31) == 0) sb[tid >> 5] = s;
    __syncthreads();
    if (tid == 0) {
        float t = 0.f;
        for (int i = 0; i < 8; i++) t += sb[i];
        if (pos >= 0) out[pos] = 1.25f * t / (float)((size_t)M * DIM);
    }
}

// ---------------- host launcher ----------------
extern "C" void kernel_launch(void* const* d_in, const int* in_sizes, int n_in,
                              void* d_out, int out_size)
{
    const float* x  = (const float*)d_in[0];
    const float* cb = (const float*)d_in[1];
    const float* W1 = (const float*)d_in[2];
    const float* b1 = (const float*)d_in[3];
    const float* W2 = (const float*)d_in[4];
    const float* b2 = (const float*)d_in[5];
    float* out = (float*)d_out;

    int M = in_sizes[0] / DIM;
    long long NQ = (long long)M * DIM;

    long long idx_off = (out_size >= NQ + M) ? NQ : -1;
    long long loss_pos = -1;
    if (out_size >= NQ + M + 1) loss_pos = NQ + M;
    else if (out_size == NQ + 1) loss_pos = NQ;

    float *p_h, *p_icb, *p_cc, *p_xx;
    __nv_bfloat16 *p_xhi, *p_xlo, *p_chi, *p_clo;
    cudaGetSymbolAddress((void**)&p_h,   g_h);
    cudaGetSymbolAddress((void**)&p_icb, g_icb);
    cudaGetSymbolAddress((void**)&p_cc,  g_cc);
    cudaGetSymbolAddress((void**)&p_xx,  g_xx);
    cudaGetSymbolAddress((void**)&p_xhi, g_xhi);
    cudaGetSymbolAddress((void**)&p_xlo, g_xlo);
    cudaGetSymbolAddress((void**)&p_chi, g_chi);
    cudaGetSymbolAddress((void**)&p_clo, g_clo);

    cudaFuncSetAttribute(dist_mma_k, cudaFuncAttributeMaxDynamicSharedMemorySize, SM_TOTAL);

    cudaMemsetAsync(d_out, 0, (size_t)out_size * sizeof(float));
    init_keys_k<<<(M + 255) / 256, 256>>>(M);

    // icb transform
    gemm128_k<<<dim3(DIM / 128, CSIZE / 128), 256>>>(cb, W1, b1, nullptr, p_h,
                                                     CSIZE, DIM, CDIM, 0);
    gemm128_k<<<dim3(DIM / 128, CSIZE / 128), 256>>>(p_h, W2, b2, p_h, p_icb,
                                                     CSIZE, DIM, DIM, 1);
    // norms
    rowsq_k<<<CSIZE, 128>>>(p_icb, p_cc);
    rowsq_k<<<M, 128>>>(x, p_xx);

    // bf16 hi/lo splits
    conv_k<<<(M * DIM / 4 + 255) / 256, 256>>>(x, p_xhi, p_xlo, M * DIM);
    conv_k<<<(CSIZE * DIM / 4 + 255) / 256, 256>>>(p_icb, p_chi, p_clo, CSIZE * DIM);

    // fused HMMA distance + argmin
    dist_mma_k<<<dim3(CSIZE / NT, M / MT), 256, SM_TOTAL>>>();

    // finish
    rowfinish_k<<<M, 128>>>(x, out, M, idx_off);
    loss_k<<<1, 256>>>(out, M, loss_pos);
}

// round 4
// speedup vs baseline: 4.0168x; 1.8966x over previous
#include <cuda_runtime.h>
#include <cuda_bf16.h>
#include <cstdint>
#include <math.h>

#define DIM   512
#define CDIM  128
#define CSIZE 8192
#define MMAX  16384
#define EPSV  1e-6f
#define CAP   64

// ---- dist kernel tiling ----
#define MT 128
#define NT 128
#define KC 32
#define NSTAGES (DIM / KC)        // 16
#define ROWB 80                   // 32 bf16 = 64B + 16B pad
#define BUFSZ (128 * ROWB)        // 10240 B
#define OFF_AHI 0
#define OFF_BHI BUFSZ
#define SM_STAGE (2 * BUFSZ)      // 20480
#define SM_BUF0 1024              // cc tile
#define SM_TOTAL (SM_BUF0 + 2 * SM_STAGE)   // 41984

// ---------------- device scratch ----------------
__device__ float g_h[CSIZE * DIM];
__device__ float g_icb[CSIZE * DIM];
__device__ float g_cc[CSIZE];
__device__ float g_xx[MMAX];
__device__ unsigned long long g_keys[MMAX];
__device__ float g_rowloss[MMAX];
__device__ __nv_bfloat16 g_xhi[MMAX * DIM];
__device__ __nv_bfloat16 g_chi[CSIZE * DIM];
__device__ unsigned int g_rowmin[MMAX];      // ordered-float running min
__device__ unsigned int g_ccount[MMAX];
__device__ int g_cand[MMAX * CAP];
__device__ float g_maxcc;

// ---------------- helpers ----------------
__device__ __forceinline__ uint32_t smem_u32(const void* p) {
    uint32_t a;
    asm("{ .reg .u64 t; cvta.to.shared.u64 t, %1; cvt.u32.u64 %0, t; }"
        : "=r"(a) : "l"(p));
    return a;
}

#define CP_ASYNC16(dst, src) \
    asm volatile("cp.async.cg.shared.global [%0], [%1], 16;" :: "r"(dst), "l"(src))
#define CP_COMMIT() asm volatile("cp.async.commit_group;" ::: "memory")
#define CP_WAIT1() asm volatile("cp.async.wait_group 1;" ::: "memory")
#define CP_WAIT0() asm volatile("cp.async.wait_group 0;" ::: "memory")

__device__ __forceinline__ void ldm_x4(uint32_t* r, uint32_t addr) {
    asm volatile("ldmatrix.sync.aligned.m8n8.x4.shared.b16 {%0,%1,%2,%3}, [%4];"
                 : "=r"(r[0]), "=r"(r[1]), "=r"(r[2]), "=r"(r[3]) : "r"(addr));
}
__device__ __forceinline__ void ldm_x2(uint32_t* r, uint32_t addr) {
    asm volatile("ldmatrix.sync.aligned.m8n8.x2.shared.b16 {%0,%1}, [%2];"
                 : "=r"(r[0]), "=r"(r[1]) : "r"(addr));
}
__device__ __forceinline__ void mma_bf16(float* c, const uint32_t* a, const uint32_t* b) {
    asm volatile(
        "mma.sync.aligned.m16n8k16.row.col.f32.bf16.bf16.f32 "
        "{%0,%1,%2,%3}, {%4,%5,%6,%7}, {%8,%9}, {%0,%1,%2,%3};"
        : "+f"(c[0]), "+f"(c[1]), "+f"(c[2]), "+f"(c[3])
        : "r"(a[0]), "r"(a[1]), "r"(a[2]), "r"(a[3]), "r"(b[0]), "r"(b[1]));
}

__device__ __forceinline__ unsigned int ord_enc(float f) {
    unsigned int u = __float_as_uint(f);
    return (u & 0x80000000u) ? ~u : (u | 0x80000000u);
}
__device__ __forceinline__ float ord_dec(unsigned int e) {
    unsigned int u = (e & 0x80000000u) ? (e & 0x7fffffffu) : ~e;
    return __uint_as_float(u);
}

__device__ __forceinline__ float selu_f(float z) {
    const float a = 1.6732632423543772f;
    const float s = 1.0507009873554805f;
    return s * (z > 0.f ? z : a * expm1f(z));
}

// ---------------- init ----------------
__global__ void init_k(int M) {
    int i = blockIdx.x * blockDim.x + threadIdx.x;
    if (i < M) { g_rowmin[i] = 0xFFFFFFFFu; g_ccount[i] = 0u; }
}

// ---------------- fp32 -> bf16 (hi only) ----------------
__global__ void convh_k(const float* __restrict__ s, __nv_bfloat16* __restrict__ hi, int n) {
    int i = (blockIdx.x * blockDim.x + threadIdx.x) * 4;
    if (i >= n) return;
    float4 v = *(const float4*)(s + i);
    __nv_bfloat162 h0 = __nv_bfloat162(__float2bfloat16(v.x), __float2bfloat16(v.y));
    __nv_bfloat162 h1 = __nv_bfloat162(__float2bfloat16(v.z), __float2bfloat16(v.w));
    *(__nv_bfloat162*)(hi + i) = h0;
    *(__nv_bfloat162*)(hi + i + 2) = h1;
}

// ---------------- 128x128 SGEMM: C = f(A)@B + bias (+ Ares) ----------------
__global__ void __launch_bounds__(256) gemm128_k(
    const float* __restrict__ A, const float* __restrict__ B,
    const float* __restrict__ bias, const float* __restrict__ Ares,
    float* __restrict__ C, int M, int N, int K, int doSelu)
{
    __shared__ float As[16][128];
    __shared__ float Bs[16][128];
    int tid = threadIdx.x;
    int tx = tid & 15, ty = tid >> 4;
    int m0 = blockIdx.y * 128, n0 = blockIdx.x * 128;

    int arow = tid >> 1, ak = (tid & 1) * 8;
    int brow = tid >> 4, bcol = (tid & 15) * 8;

    float acc[8][8];
#pragma unroll
    for (int i = 0; i < 8; i++)
#pragma unroll
        for (int j = 0; j < 8; j++) acc[i][j] = 0.f;

    for (int k0 = 0; k0 < K; k0 += 16) {
        float4 a0 = *(const float4*)(A + (size_t)(m0 + arow) * K + k0 + ak);
        float4 a1 = *(const float4*)(A + (size_t)(m0 + arow) * K + k0 + ak + 4);
        if (doSelu) {
            a0.x = selu_f(a0.x); a0.y = selu_f(a0.y); a0.z = selu_f(a0.z); a0.w = selu_f(a0.w);
            a1.x = selu_f(a1.x); a1.y = selu_f(a1.y); a1.z = selu_f(a1.z); a1.w = selu_f(a1.w);
        }
        As[ak + 0][arow] = a0.x; As[ak + 1][arow] = a0.y;
        As[ak + 2][arow] = a0.z; As[ak + 3][arow] = a0.w;
        As[ak + 4][arow] = a1.x; As[ak + 5][arow] = a1.y;
        As[ak + 6][arow] = a1.z; As[ak + 7][arow] = a1.w;

        float4 b0 = *(const float4*)(B + (size_t)(k0 + brow) * N + n0 + bcol);
        float4 b1 = *(const float4*)(B + (size_t)(k0 + brow) * N + n0 + bcol + 4);
        *(float4*)&Bs[brow][bcol] = b0;
        *(float4*)&Bs[brow][bcol + 4] = b1;
        __syncthreads();

#pragma unroll
        for (int k = 0; k < 16; k++) {
            float a[8], b[8];
#pragma unroll
            for (int i = 0; i < 8; i++) a[i] = As[k][ty * 8 + i];
#pragma unroll
            for (int j = 0; j < 8; j++) b[j] = Bs[k][tx * 8 + j];
#pragma unroll
            for (int i = 0; i < 8; i++)
#pragma unroll
                for (int j = 0; j < 8; j++) acc[i][j] += a[i] * b[j];
        }
        __syncthreads();
    }

#pragma unroll
    for (int i = 0; i < 8; i++) {
        int m = m0 + ty * 8 + i;
#pragma unroll
        for (int j = 0; j < 8; j++) {
            int n = n0 + tx * 8 + j;
            float v = acc[i][j] + bias[n];
            if (Ares) v += Ares[(size_t)m * N + n];
            C[(size_t)m * N + n] = v;
        }
    }
}

// ---------------- per-row sum of squares ----------------
__global__ void rowsq_k(const float* __restrict__ A, float* __restrict__ outv) {
    int m = blockIdx.x;
    int tid = threadIdx.x;
    const float* r = A + (size_t)m * DIM;
    float s = 0.f;
#pragma unroll
    for (int i = 0; i < 4; i++) { float v = r[tid + i * 128]; s += v * v; }
    for (int o = 16; o > 0; o >>= 1) s += __shfl_down_sync(0xffffffffu, s, o);
    __shared__ float sb[4];
    if ((tid & 31) == 0) sb[tid >> 5] = s;
    __syncthreads();
    if (tid == 0) outv[m] = sb[0] + sb[1] + sb[2] + sb[3];
}

// ---------------- max of g_cc ----------------
__global__ void maxcc_k() {
    int tid = threadIdx.x;   // 256
    float mx = 0.f;
    for (int i = tid; i < CSIZE; i += 256) mx = fmaxf(mx, g_cc[i]);
    for (int o = 16; o > 0; o >>= 1) mx = fmaxf(mx, __shfl_down_sync(0xffffffffu, mx, o));
    __shared__ float sb[8];
    if ((tid & 31) == 0) sb[tid >> 5] = mx;
    __syncthreads();
    if (tid == 0) {
        float t = sb[0];
        for (int i = 1; i < 8; i++) t = fmaxf(t, sb[i]);
        g_maxcc = t;
    }
}

// ---------------- Phase 1: approx bf16 distance GEMM + candidate filter ----
__global__ void __launch_bounds__(256) dist_mma_k() {
    extern __shared__ char smem[];
    uint32_t sbase = smem_u32(smem);
    float* s_cc = (float*)smem;

    int tid = threadIdx.x;
    int wid = tid >> 5, lane = tid & 31;
    int bn = blockIdx.x * NT;
    int bm = blockIdx.y * MT;

    int wm = (wid & 3) * 32;
    int wn = (wid >> 2) * 64;

    if (tid < NT) s_cc[tid] = g_cc[bn + tid];
    float maxcc = g_maxcc;

    float acc[2][8][4];
#pragma unroll
    for (int i = 0; i < 2; i++)
#pragma unroll
        for (int j = 0; j < 8; j++)
#pragma unroll
            for (int r = 0; r < 4; r++) acc[i][j][r] = 0.f;

    const __nv_bfloat16* xhi = g_xhi;
    const __nv_bfloat16* chi = g_chi;

    auto issue_stage = [&](int s) {
        int b = s & 1;
        int k0 = s * KC;
        uint32_t buf = sbase + SM_BUF0 + b * SM_STAGE;
#pragma unroll
        for (int r = 0; r < 2; r++) {
            int c = tid + 256 * r;
            int row = c >> 2, part = c & 3;
            uint32_t so = (uint32_t)(row * ROWB + part * 16);
            size_t goA = (size_t)(bm + row) * DIM + k0 + part * 8;
            size_t goB = (size_t)(bn + row) * DIM + k0 + part * 8;
            CP_ASYNC16(buf + OFF_AHI + so, xhi + goA);
            CP_ASYNC16(buf + OFF_BHI + so, chi + goB);
        }
    };

    issue_stage(0);
    CP_COMMIT();

    for (int s = 0; s < NSTAGES; s++) {
        if (s + 1 < NSTAGES) {
            issue_stage(s + 1);
            CP_COMMIT();
            CP_WAIT1();
        } else {
            CP_WAIT0();
        }
        __syncthreads();

        uint32_t buf = sbase + SM_BUF0 + (s & 1) * SM_STAGE;
#pragma unroll
        for (int kk = 0; kk < 2; kk++) {
            int kb = kk * 32;
            uint32_t arow = (uint32_t)((wm + (lane & 15)) * ROWB + kb + (lane >> 4) * 16);
            uint32_t ahi0[4], ahi1[4];
            ldm_x4(ahi0, buf + OFF_AHI + arow);
            ldm_x4(ahi1, buf + OFF_AHI + arow + 16 * ROWB);

            uint32_t brow_base =
                (uint32_t)((wn + (lane & 7)) * ROWB + kb + ((lane >> 3) & 1) * 16);
#pragma unroll
            for (int j = 0; j < 8; j++) {
                uint32_t bo = brow_base + (uint32_t)(j * 8 * ROWB);
                uint32_t bhi[2];
                ldm_x2(bhi, buf + OFF_BHI + bo);
                mma_bf16(acc[0][j], ahi0, bhi);
                mma_bf16(acc[1][j], ahi1, bhi);
            }
        }
        __syncthreads();
    }

    // -------- epilogue: approx d2, running rowmin, candidate push --------
    int q = lane >> 2, t = lane & 3;
#pragma unroll
    for (int i = 0; i < 2; i++) {
#pragma unroll
        for (int h = 0; h < 2; h++) {
            int row = bm + wm + i * 16 + h * 8 + q;
            float xxv = g_xx[row];
            float d2s[16];
            float best = 3.4e38f;
#pragma unroll
            for (int j = 0; j < 8; j++) {
#pragma unroll
                for (int e = 0; e < 2; e++) {
                    float dot = acc[i][j][h * 2 + e];
                    float d2 = __fadd_rn(__fadd_rn(xxv, __fmul_rn(dot, -2.0f)),
                                         s_cc[wn + j * 8 + 2 * t + e]);
                    d2s[j * 2 + e] = d2;
                    best = fminf(best, d2);
                }
            }
            unsigned int fb = ord_enc(best);
            unsigned int o1 = __shfl_xor_sync(0xffffffffu, fb, 1);
            fb = (o1 < fb) ? o1 : fb;
            unsigned int o2 = __shfl_xor_sync(0xffffffffu, fb, 2);
            fb = (o2 < fb) ? o2 : fb;
            unsigned int old = 0xFFFFFFFFu;
            if (t == 0) old = atomicMin(&g_rowmin[row], fb);
            old = __shfl_sync(0xffffffffu, old, lane & ~3);
            unsigned int run = (old < fb) ? old : fb;
            float thr = ord_dec(run) + (2.f * sqrtf(xxv * maxcc) * 0.0078125f + 0.01f);
#pragma unroll
            for (int j = 0; j < 8; j++) {
#pragma unroll
                for (int e = 0; e < 2; e++) {
                    if (d2s[j * 2 + e] < thr) {
                        unsigned int slot = atomicAdd(&g_ccount[row], 1u);
                        if (slot < CAP)
                            g_cand[row * CAP + slot] = bn + wn + j * 8 + 2 * t + e;
                    }
                }
            }
        }
    }
}

// ---------------- Phase 2: exact fp32 refine over candidates ----------------
__global__ void refine_k(const float* __restrict__ X) {
    int m = blockIdx.x;
    int tid = threadIdx.x;   // 128
    unsigned int cnt = g_ccount[m];
    float xxv = g_xx[m];
    const float* xr = X + (size_t)m * DIM;

    float xv[4];
#pragma unroll
    for (int i = 0; i < 4; i++) xv[i] = xr[tid + i * 128];

    __shared__ float sred[4];
    __shared__ unsigned long long s_best;
    if (tid == 0) s_best = ~0ULL;
    __syncthreads();

    bool fullscan = (cnt == 0u) || (cnt > (unsigned)CAP);
    int n_iter = fullscan ? CSIZE : (int)cnt;

    for (int s = 0; s < n_iter; s++) {
        int c = fullscan ? s : g_cand[m * CAP + s];
        const float* cr = g_icb + (size_t)c * DIM;
        float p = 0.f;
#pragma unroll
        for (int i = 0; i < 4; i++) p += xv[i] * cr[tid + i * 128];
        for (int o = 16; o > 0; o >>= 1) p += __shfl_down_sync(0xffffffffu, p, o);
        if ((tid & 31) == 0) sred[tid >> 5] = p;
        __syncthreads();
        if (tid == 0) {
            float dot = sred[0] + sred[1] + sred[2] + sred[3];
            float d2 = __fadd_rn(__fadd_rn(xxv, __fmul_rn(dot, -2.0f)), g_cc[c]);
            unsigned long long key =
                ((unsigned long long)ord_enc(d2) << 32) | (unsigned)c;
            if (key < s_best) s_best = key;
        }
        __syncthreads();
    }
    if (tid == 0) g_keys[m] = s_best;
}

// ---------------- gather + Householder rotation + loss ----------------
__global__ void rowfinish_k(const float* __restrict__ X, float* __restrict__ out,
                            int M, long long idx_off)
{
    int m = blockIdx.x;
    int tid = threadIdx.x;
    unsigned long long key = g_keys[m];
    int idx = (int)(key & 0xffffffffu);

    const float* xr = X + (size_t)m * DIM;
    const float* qr = g_icb + (size_t)idx * DIM;

    float xv[4], qv[4];
    float sx2 = 0.f, sq2 = 0.f, sd2 = 0.f;
#pragma unroll
    for (int i = 0; i < 4; i++) {
        int d = tid + i * 128;
        xv[i] = xr[d]; qv[i] = qr[d];
        sx2 += xv[i] * xv[i];
        sq2 += qv[i] * qv[i];
        float df = xv[i] - qv[i];
        sd2 += df * df;
    }

    __shared__ float sb[16];
    {
        float v0 = sx2, v1 = sq2, v2 = sd2;
        for (int o = 16; o > 0; o >>= 1) {
            v0 += __shfl_down_sync(0xffffffffu, v0, o);
            v1 += __shfl_down_sync(0xffffffffu, v1, o);
            v2 += __shfl_down_sync(0xffffffffu, v2, o);
        }
        int w = tid >> 5;
        if ((tid & 31) == 0) { sb[w] = v0; sb[4 + w] = v1; sb[8 + w] = v2; }
        __syncthreads();
        sx2 = sb[0] + sb[1] + sb[2] + sb[3];
        sq2 = sb[4] + sb[5] + sb[6] + sb[7];
        sd2 = sb[8] + sb[9] + sb[10] + sb[11];
        __syncthreads();
    }

    float ns = sqrtf(sx2), nt = sqrtf(sq2);
    float ins = 1.f / fmaxf(ns, EPSV);
    float inv_t = 1.f / fmaxf(nt, EPSV);

    float wv[4];
    float sw2 = 0.f, sxw = 0.f;
#pragma unroll
    for (int i = 0; i < 4; i++) {
        float w = xv[i] * ins + qv[i] * inv_t;
        wv[i] = w;
        sw2 += w * w;
        sxw += xv[i] * w;
    }
    {
        float v0 = sw2, v1 = sxw;
        for (int o = 16; o > 0; o >>= 1) {
            v0 += __shfl_down_sync(0xffffffffu, v0, o);
            v1 += __shfl_down_sync(0xffffffffu, v1, o);
        }
        int w = tid >> 5;
        if ((tid & 31) == 0) { sb[w] = v0; sb[4 + w] = v1; }
        __syncthreads();
        sw2 = sb[0] + sb[1] + sb[2] + sb[3];
        sxw = sb[4] + sb[5] + sb[6] + sb[7];
        __syncthreads();
    }

    float iwn = 1.f / fmaxf(sqrtf(sw2), EPSV);
    float xdw = sxw * iwn;
    float xdu = sx2 * ins;
    float scl = nt * ins;

    float* orow = out + (size_t)m * DIM;
#pragma unroll
    for (int i = 0; i < 4; i++) {
        int d = tid + i * 128;
        float r = xv[i] - 2.f * xdw * (wv[i] * iwn) + 2.f * xdu * (qv[i] * inv_t);
        orow[d] = r * scl;
    }

    if (tid == 0) {
        g_rowloss[m] = sd2;
        if (idx_off >= 0) out[idx_off + m] = (float)idx;
    }
}

__global__ void loss_k(float* __restrict__ out, int M, long long pos) {
    int tid = threadIdx.x;
    float s = 0.f;
    for (int i = tid; i < M; i += 256) s += g_rowloss[i];
    for (int o = 16; o > 0; o >>= 1) s += __shfl_down_sync(0xffffffffu, s, o);
    __shared__ float sb[8];
    if ((tid & 31) == 0) sb[tid >> 5] = s;
    __syncthreads();
    if (tid == 0) {
        float t = 0.f;
        for (int i = 0; i < 8; i++) t += sb[i];
        if (pos >= 0) out[pos] = 1.25f * t / (float)((size_t)M * DIM);
    }
}

// ---------------- host launcher ----------------
extern "C" void kernel_launch(void* const* d_in, const int* in_sizes, int n_in,
                              void* d_out, int out_size)
{
    const float* x  = (const float*)d_in[0];
    const float* cb = (const float*)d_in[1];
    const float* W1 = (const float*)d_in[2];
    const float* b1 = (const float*)d_in[3];
    const float* W2 = (const float*)d_in[4];
    const float* b2 = (const float*)d_in[5];
    float* out = (float*)d_out;

    int M = in_sizes[0] / DIM;
    long long NQ = (long long)M * DIM;

    long long idx_off = (out_size >= NQ + M) ? NQ : -1;
    long long loss_pos = -1;
    if (out_size >= NQ + M + 1) loss_pos = NQ + M;
    else if (out_size == NQ + 1) loss_pos = NQ;

    float *p_h, *p_icb, *p_cc, *p_xx;
    __nv_bfloat16 *p_xhi, *p_chi;
    cudaGetSymbolAddress((void**)&p_h,   g_h);
    cudaGetSymbolAddress((void**)&p_icb, g_icb);
    cudaGetSymbolAddress((void**)&p_cc,  g_cc);
    cudaGetSymbolAddress((void**)&p_xx,  g_xx);
    cudaGetSymbolAddress((void**)&p_xhi, g_xhi);
    cudaGetSymbolAddress((void**)&p_chi, g_chi);

    cudaFuncSetAttribute(dist_mma_k, cudaFuncAttributeMaxDynamicSharedMemorySize, SM_TOTAL);

    cudaMemsetAsync(d_out, 0, (size_t)out_size * sizeof(float));
    init_k<<<(M + 255) / 256, 256>>>(M);

    // icb transform
    gemm128_k<<<dim3(DIM / 128, CSIZE / 128), 256>>>(cb, W1, b1, nullptr, p_h,
                                                     CSIZE, DIM, CDIM, 0);
    gemm128_k<<<dim3(DIM / 128, CSIZE / 128), 256>>>(p_h, W2, b2, p_h, p_icb,
                                                     CSIZE, DIM, DIM, 1);
    // norms + margin bound
    rowsq_k<<<CSIZE, 128>>>(p_icb, p_cc);
    rowsq_k<<<M, 128>>>(x, p_xx);
    maxcc_k<<<1, 256>>>();

    // bf16 casts (hi only)
    convh_k<<<(M * DIM / 4 + 255) / 256, 256>>>(x, p_xhi, M * DIM);
    convh_k<<<(CSIZE * DIM / 4 + 255) / 256, 256>>>(p_icb, p_chi, CSIZE * DIM);

    // phase 1: approx distances + candidates
    dist_mma_k<<<dim3(CSIZE / NT, M / MT), 256, SM_TOTAL>>>();
    // phase 2: exact refine
    refine_k<<<M, 128>>>(x);

    // finish
    rowfinish_k<<<M, 128>>>(x, out, M, idx_off);
    loss_k<<<1, 256>>>(out, M, loss_pos);
}